// round 10
// baseline (speedup 1.0000x reference)
#include <cuda_runtime.h>
#include <cuda_bf16.h>
#include <math.h>

// ---------------- problem constants ----------------
#define BATCH 256
#define GENES 4000
#define PATH  128      // P
#define OMICS 3
#define DDIM  (OMICS * GENES)   // 12000
#define HDIM  64
#define ODIM  16
#define GHID  128      // gate hidden
#define CHID  8
#define NCLS  5
#define TOPK  3
#define BNEPS 1e-5f
#define NENT  (BATCH * TOPK)    // 768 expert work items
#define MAXTILE 288             // max sum of ceil(cnt_p/4)
#define NSEG  4                 // gene-split factor

// gate GEMM split-K config
#define KSPLIT 50
#define KC     80     // 50*80 = 4000
#define KB     16
#define GEMM_BLOCKS (BATCH / 64 * KSPLIT)   // 200
#define K1_BLOCKS (GEMM_BLOCKS + PATH)      // 328

// ---------------- device scratch (no allocations allowed) ----------------
__device__ float g_partial[KSPLIT * BATCH * GHID];
__device__ int   g_gene_idx[PATH * GENES];
__device__ int   g_gene_cnt[PATH];
__device__ int   g_entry[NENT];
__device__ float g_wt[NENT];
__device__ int   g_sorted[NENT];
__device__ int   g_tile_p[MAXTILE];
__device__ int   g_tile_s0[MAXTILE];
__device__ int   g_tile_n[MAXTILE];
__device__ int   g_ntiles;
__device__ float g_hpart[MAXTILE * NSEG * 4 * HDIM];   // partial h per (tile, seg, sample)
__device__ float g_contrib[NENT * ODIM];

// =============== K1: fused gene-list compaction + gate GEMM ===============
__global__ void __launch_bounds__(256)
k1_fused(const float* __restrict__ gene_mask,
         const float* __restrict__ x,
         const float* __restrict__ w) {
    __shared__ float As[KB][64];
    __shared__ float Bs[KB][GHID];
    __shared__ int sbase;
    __shared__ int wcnt[8];
    __shared__ int woff[8];

    int t = threadIdx.x;

    if (blockIdx.x < GEMM_BLOCKS) {
        int b0 = (blockIdx.x & 3) * 64;
        int k0 = (blockIdx.x >> 2) * KC;
        int rgrp = t >> 5;
        int cgrp = t & 31;

        float acc[8][4];
        #pragma unroll
        for (int i = 0; i < 8; i++)
            #pragma unroll
            for (int j = 0; j < 4; j++) acc[i][j] = 0.0f;

        for (int kb = 0; kb < KC; kb += KB) {
            int kbase = k0 + kb;
            {
                int r = t >> 2;
                int kq = (t & 3) * 4;
                float4 av = *reinterpret_cast<const float4*>(
                    x + (size_t)(b0 + r) * GENES + kbase + kq);
                As[kq + 0][r] = av.x; As[kq + 1][r] = av.y;
                As[kq + 2][r] = av.z; As[kq + 3][r] = av.w;
            }
            #pragma unroll
            for (int i = 0; i < 2; i++) {
                int f = t + i * 256;
                int kk = f >> 5;
                int c = (f & 31) * 4;
                *reinterpret_cast<float4*>(&Bs[kk][c]) =
                    *reinterpret_cast<const float4*>(w + (size_t)(kbase + kk) * GHID + c);
            }
            __syncthreads();
            #pragma unroll
            for (int kk = 0; kk < KB; kk++) {
                float4 b4 = *reinterpret_cast<const float4*>(&Bs[kk][cgrp * 4]);
                float4 a0 = *reinterpret_cast<const float4*>(&As[kk][rgrp * 8]);
                float4 a1 = *reinterpret_cast<const float4*>(&As[kk][rgrp * 8 + 4]);
                float av[8] = {a0.x, a0.y, a0.z, a0.w, a1.x, a1.y, a1.z, a1.w};
                float bv[4] = {b4.x, b4.y, b4.z, b4.w};
                #pragma unroll
                for (int i = 0; i < 8; i++)
                    #pragma unroll
                    for (int j = 0; j < 4; j++)
                        acc[i][j] = fmaf(av[i], bv[j], acc[i][j]);
            }
            __syncthreads();
        }
        float* out = g_partial + (size_t)(blockIdx.x >> 2) * (BATCH * GHID);
        #pragma unroll
        for (int i = 0; i < 8; i++) {
            *reinterpret_cast<float4*>(
                out + (size_t)(b0 + rgrp * 8 + i) * GHID + cgrp * 4) =
                make_float4(acc[i][0], acc[i][1], acc[i][2], acc[i][3]);
        }
    } else {
        int p = blockIdx.x - GEMM_BLOCKS;
        int wid = t >> 5, lane = t & 31;
        if (t == 0) sbase = 0;
        __syncthreads();
        for (int g0 = 0; g0 < GENES; g0 += 256) {
            int g = g0 + t;
            bool pred = (g < GENES) && (gene_mask[(size_t)g * PATH + p] != 0.0f);
            unsigned m = __ballot_sync(0xffffffffu, pred);
            if (lane == 0) wcnt[wid] = __popc(m);
            __syncthreads();
            if (t == 0) {
                int s = sbase;
                #pragma unroll
                for (int w8 = 0; w8 < 8; w8++) { woff[w8] = s; s += wcnt[w8]; }
                sbase = s;
            }
            __syncthreads();
            if (pred) {
                int pos = woff[wid] + __popc(m & ((1u << lane) - 1u));
                g_gene_idx[p * GENES + pos] = g;
            }
            __syncthreads();
        }
        if (t == 0) g_gene_cnt[p] = sbase;
    }
}

// =============== K2: fused gate finish (reduce + relu + layer2 + top3) ===============
__global__ void __launch_bounds__(128)
k2_gate_finish(const float* __restrict__ gb1,
               const float* __restrict__ w2,
               const float* __restrict__ b2g,
               float* __restrict__ out_gw) {
    __shared__ float hid[GHID];
    __shared__ float lg[PATH];
    __shared__ float sv[TOPK];
    __shared__ int   si[TOPK];
    int b = blockIdx.x;
    int p = threadIdx.x;

    float s = 0.0f;
    #pragma unroll
    for (int sp = 0; sp < KSPLIT; sp++)
        s += g_partial[(size_t)sp * (BATCH * GHID) + b * GHID + p];
    s += gb1[p];
    hid[p] = fmaxf(s, 0.0f);
    __syncthreads();

    float acc = b2g[p];
    #pragma unroll 8
    for (int k = 0; k < GHID; k++)
        acc = fmaf(hid[k], __ldg(w2 + (size_t)k * PATH + p), acc);
    lg[p] = acc;
    __syncthreads();

    if (p < 32) {
        float v[4];
        #pragma unroll
        for (int q = 0; q < 4; q++) v[q] = lg[p + q * 32];
        #pragma unroll
        for (int k = 0; k < TOPK; k++) {
            float bv = -1e30f; int bi = 0x7fffffff;
            #pragma unroll
            for (int q = 0; q < 4; q++) {
                int idq = p + q * 32;
                if (v[q] > bv || (v[q] == bv && idq < bi)) { bv = v[q]; bi = idq; }
            }
            #pragma unroll
            for (int off = 16; off; off >>= 1) {
                float ov = __shfl_xor_sync(0xffffffffu, bv, off);
                int oi = __shfl_xor_sync(0xffffffffu, bi, off);
                if (ov > bv || (ov == bv && oi < bi)) { bv = ov; bi = oi; }
            }
            if (p == 0) { sv[k] = bv; si[k] = bi; }
            #pragma unroll
            for (int q = 0; q < 4; q++)
                if (p + q * 32 == bi) v[q] = -1e30f;
        }
    }
    __syncthreads();

    float val = 0.0f;
    #pragma unroll
    for (int k = 0; k < TOPK; k++)
        if (si[k] == p) val = 1.0f / (1.0f + expf(-sv[k]));
    out_gw[(size_t)b * PATH + p] = val;
    if (p < TOPK) {
        g_entry[b * TOPK + p] = si[p];
        g_wt[b * TOPK + p] = 1.0f / (1.0f + expf(-sv[p]));
    }
}

// =============== K3: fast sort (1 block, 128 threads, no atomics) ===============
__global__ void __launch_bounds__(128)
k3_sort() {
    __shared__ int ent_s[NENT];
    __shared__ int wsumC[4], wsumT[4];
    int tid = threadIdx.x;

    for (int e = tid; e < NENT; e += 128) ent_s[e] = g_entry[e];
    __syncthreads();

    int p = tid;
    int cnt = 0;
    for (int e = 0; e < NENT; e++) cnt += (ent_s[e] == p);
    int nt = (cnt + 3) >> 2;

    int lane = tid & 31, wrp = tid >> 5;
    int incC = cnt, incT = nt;
    #pragma unroll
    for (int o = 1; o < 32; o <<= 1) {
        int cc = __shfl_up_sync(0xffffffffu, incC, o);
        int tt = __shfl_up_sync(0xffffffffu, incT, o);
        if (lane >= o) { incC += cc; incT += tt; }
    }
    if (lane == 31) { wsumC[wrp] = incC; wsumT[wrp] = incT; }
    __syncthreads();
    int baseC = 0, baseT = 0;
    #pragma unroll
    for (int wv = 0; wv < 4; wv++)
        if (wv < wrp) { baseC += wsumC[wv]; baseT += wsumT[wv]; }
    int offp  = baseC + incC - cnt;
    int toffp = baseT + incT - nt;

    int pos = offp;
    for (int e = 0; e < NENT; e++)
        if (ent_s[e] == p) g_sorted[pos++] = e;
    for (int tt = 0; tt < nt; tt++) {
        int idx = toffp + tt;
        g_tile_p[idx] = p;
        g_tile_s0[idx] = offp + 4 * tt;
        int rem = cnt - 4 * tt;
        g_tile_n[idx] = rem < 4 ? rem : 4;
    }
    __syncthreads();
    if (tid == 0)
        g_ntiles = wsumT[0] + wsumT[1] + wsumT[2] + wsumT[3];
}

// =============== K4: sparse experts — barrier-free pipelined stream ===============
// block = (tile, gene-segment). 8 warps; lane owns h = 2*lane, 2*lane+1.
// Per row: 1 glist broadcast LDG + 1 coalesced float2 W1 LDG + 4 broadcast x LDGs
// + 8 FMA, with a depth-2 register prefetch pipeline. No smem staging, no
// mid-kernel barriers — only the final cross-warp reduce syncs.
__global__ void __launch_bounds__(256)
k4_expert(const float* __restrict__ x_rna,
          const float* __restrict__ x_cnv,
          const float* __restrict__ x_met,
          const float* __restrict__ W1) {
    int blk = blockIdx.x;
    int tnum = blk >> 2;
    int seg  = blk & 3;
    if (tnum >= g_ntiles) return;
    int p  = g_tile_p[tnum];
    int s0 = g_tile_s0[tnum];
    int n  = g_tile_n[tnum];
    if (n <= 0) return;
    int ng = g_gene_cnt[p];
    int qs = (ng * seg) >> 2;
    int qe = (ng * (seg + 1)) >> 2;

    int tid = threadIdx.x;
    int lane = tid & 31;   // h columns 2*lane, 2*lane+1
    int wrp = tid >> 5;    // warp owns genes i = qs+wrp, +8, ...

    __shared__ float red[8 * 4 * HDIM]; // [warp][sample][h]
    __shared__ int   bsh[4];

    if (tid < 4) {
        int sl = tid < n ? tid : n - 1;
        bsh[tid] = g_sorted[s0 + sl] / TOPK;
    }
    __syncthreads();
    int b0s = bsh[0], b1s = bsh[1], b2s = bsh[2], b3s = bsh[3];

    const int* glist = g_gene_idx + p * GENES;
    const float* W1p = W1 + (size_t)p * DDIM * HDIM + 2 * lane;

    float acc[2][4];   // [h-of-pair][sample]
    #pragma unroll
    for (int i = 0; i < 2; i++)
        #pragma unroll
        for (int j = 0; j < 4; j++) acc[i][j] = 0.0f;

    #pragma unroll
    for (int omic = 0; omic < OMICS; omic++) {
        const float* xp = (omic == 0) ? x_rna : (omic == 1) ? x_cnv : x_met;
        const float* Wo = W1p + (size_t)omic * GENES * HDIM;

        int i = qs + wrp;
        float2 wv = make_float2(0.0f, 0.0f);
        float4 xv = make_float4(0.0f, 0.0f, 0.0f, 0.0f);
        if (i < qe) {
            int g = __ldg(glist + i);
            wv = *reinterpret_cast<const float2*>(Wo + (size_t)g * HDIM);
            xv.x = __ldg(xp + (size_t)b0s * GENES + g);
            xv.y = __ldg(xp + (size_t)b1s * GENES + g);
            xv.z = __ldg(xp + (size_t)b2s * GENES + g);
            xv.w = __ldg(xp + (size_t)b3s * GENES + g);
        }
        while (i < qe) {
            int i2 = i + 8;
            float2 wv2 = make_float2(0.0f, 0.0f);
            float4 xv2 = make_float4(0.0f, 0.0f, 0.0f, 0.0f);
            if (i2 < qe) {
                int g2 = __ldg(glist + i2);
                wv2 = *reinterpret_cast<const float2*>(Wo + (size_t)g2 * HDIM);
                xv2.x = __ldg(xp + (size_t)b0s * GENES + g2);
                xv2.y = __ldg(xp + (size_t)b1s * GENES + g2);
                xv2.z = __ldg(xp + (size_t)b2s * GENES + g2);
                xv2.w = __ldg(xp + (size_t)b3s * GENES + g2);
            }
            acc[0][0] = fmaf(wv.x, xv.x, acc[0][0]);
            acc[0][1] = fmaf(wv.x, xv.y, acc[0][1]);
            acc[0][2] = fmaf(wv.x, xv.z, acc[0][2]);
            acc[0][3] = fmaf(wv.x, xv.w, acc[0][3]);
            acc[1][0] = fmaf(wv.y, xv.x, acc[1][0]);
            acc[1][1] = fmaf(wv.y, xv.y, acc[1][1]);
            acc[1][2] = fmaf(wv.y, xv.z, acc[1][2]);
            acc[1][3] = fmaf(wv.y, xv.w, acc[1][3]);
            wv = wv2; xv = xv2; i = i2;
        }
    }

    // store per-warp partials: red[wrp][sm][h] (float2, 8B aligned)
    #pragma unroll
    for (int sm = 0; sm < 4; sm++) {
        *reinterpret_cast<float2*>(
            &red[(wrp * 4 + sm) * HDIM + 2 * lane]) =
            make_float2(acc[0][sm], acc[1][sm]);
    }
    __syncthreads();

    // reduce across 8 warps (ascending order, deterministic): thread = (sm, hh)
    {
        int sm = tid >> 6;      // 0..3
        int hh = tid & 63;
        float a = 0.0f;
        #pragma unroll
        for (int w8 = 0; w8 < 8; w8++)
            a += red[(w8 * 4 + sm) * HDIM + hh];
        float* hp = g_hpart + ((size_t)(tnum * NSEG + seg) * 4) * HDIM;
        hp[sm * HDIM + hh] = a;
    }
}

// =============== K4b: finish — reduce segments + BN + ReLU + W2 + weight ===============
__global__ void __launch_bounds__(256)
k4b_finish(const float* __restrict__ b1,
           const float* __restrict__ bn_gamma,
           const float* __restrict__ bn_beta,
           const float* __restrict__ bn_mean,
           const float* __restrict__ bn_var,
           const float* __restrict__ W2,
           const float* __restrict__ b2) {
    int tnum = blockIdx.x;
    if (tnum >= g_ntiles) return;
    int p  = g_tile_p[tnum];
    int s0 = g_tile_s0[tnum];
    int n  = g_tile_n[tnum];
    if (n <= 0) return;
    int tid = threadIdx.x;

    __shared__ float hsm[4][HDIM];
    __shared__ float w2s[HDIM * ODIM];
    __shared__ int   es[4];

    if (tid < 4) {
        int sl = tid < n ? tid : n - 1;
        es[tid] = g_sorted[s0 + sl];
    }
    const float* W2p = W2 + (size_t)p * HDIM * ODIM;
    for (int j = tid; j < HDIM * ODIM; j += 256) w2s[j] = W2p[j];

    {
        int sm = tid >> 6;       // 0..3
        int hh = tid & 63;
        const float* hp = g_hpart + (size_t)tnum * NSEG * 4 * HDIM;
        float a = 0.0f;
        #pragma unroll
        for (int q = 0; q < NSEG; q++)
            a += hp[(q * 4 + sm) * HDIM + hh];
        a += b1[p * HDIM + hh];
        float scale = bn_gamma[p * HDIM + hh] * rsqrtf(bn_var[p * HDIM + hh] + BNEPS);
        a = (a - bn_mean[p * HDIM + hh]) * scale + bn_beta[p * HDIM + hh];
        hsm[sm][hh] = fmaxf(a, 0.0f);
    }
    __syncthreads();

    if (tid < 64) {
        int sm = tid >> 4;
        int o = tid & 15;
        if (sm < n) {
            float sum = 0.0f;
            #pragma unroll 8
            for (int h2 = 0; h2 < HDIM; h2++)
                sum = fmaf(hsm[sm][h2], w2s[h2 * ODIM + o], sum);
            sum += b2[p * ODIM + o];
            int e = es[sm];
            g_contrib[(size_t)e * ODIM + o] = sum * g_wt[e];
        }
    }
}

// =============== K5: classifier ===============
__global__ void __launch_bounds__(256)
k5_classifier(const float* __restrict__ cw1,
              const float* __restrict__ cb1,
              const float* __restrict__ cw2,
              const float* __restrict__ cb2,
              float* __restrict__ out_logits) {
    int b = threadIdx.x;
    float feat[ODIM];
    #pragma unroll
    for (int o = 0; o < ODIM; o++)
        feat[o] = g_contrib[((size_t)b * TOPK + 0) * ODIM + o]
                + g_contrib[((size_t)b * TOPK + 1) * ODIM + o]
                + g_contrib[((size_t)b * TOPK + 2) * ODIM + o];
    float h8[CHID];
    #pragma unroll
    for (int c = 0; c < CHID; c++) {
        float s = cb1[c];
        #pragma unroll
        for (int o = 0; o < ODIM; o++)
            s = fmaf(feat[o], __ldg(cw1 + o * CHID + c), s);
        h8[c] = fmaxf(s, 0.0f);
    }
    #pragma unroll
    for (int c5 = 0; c5 < NCLS; c5++) {
        float s = cb2[c5];
        #pragma unroll
        for (int c = 0; c < CHID; c++)
            s = fmaf(h8[c], __ldg(cw2 + c * NCLS + c5), s);
        out_logits[(size_t)b * NCLS + c5] = s;
    }
}

// ---------------- launch ----------------
extern "C" void kernel_launch(void* const* d_in, const int* in_sizes, int n_in,
                              void* d_out, int out_size) {
    const float* x_rna    = (const float*)d_in[0];
    const float* x_cnv    = (const float*)d_in[1];
    const float* x_met    = (const float*)d_in[2];
    const float* gene_mask= (const float*)d_in[3];
    const float* gate_w1  = (const float*)d_in[4];
    const float* gate_b1  = (const float*)d_in[5];
    const float* gate_w2  = (const float*)d_in[6];
    const float* gate_b2  = (const float*)d_in[7];
    const float* W1       = (const float*)d_in[8];
    const float* b1       = (const float*)d_in[9];
    const float* bn_gamma = (const float*)d_in[10];
    const float* bn_beta  = (const float*)d_in[11];
    const float* bn_mean  = (const float*)d_in[12];
    const float* bn_var   = (const float*)d_in[13];
    const float* W2       = (const float*)d_in[14];
    const float* b2       = (const float*)d_in[15];
    const float* cls_w1   = (const float*)d_in[16];
    const float* cls_b1   = (const float*)d_in[17];
    const float* cls_w2   = (const float*)d_in[18];
    const float* cls_b2   = (const float*)d_in[19];
    float* out = (float*)d_out;
    float* out_logits = out;
    float* out_gw = out + BATCH * NCLS;

    k1_fused<<<K1_BLOCKS, 256>>>(gene_mask, x_rna, gate_w1);
    k2_gate_finish<<<BATCH, GHID>>>(gate_b1, gate_w2, gate_b2, out_gw);
    k3_sort<<<1, 128>>>();
    k4_expert<<<MAXTILE * NSEG, 256>>>(x_rna, x_cnv, x_met, W1);
    k4b_finish<<<MAXTILE, 256>>>(b1, bn_gamma, bn_beta, bn_mean, bn_var, W2, b2);
    k5_classifier<<<1, BATCH>>>(cls_w1, cls_b1, cls_w2, cls_b2, out_logits);
}

// round 11
// speedup vs baseline: 1.0501x; 1.0501x over previous
#include <cuda_runtime.h>
#include <cuda_bf16.h>
#include <math.h>

// ---------------- problem constants ----------------
#define BATCH 256
#define GENES 4000
#define PATH  128      // P
#define OMICS 3
#define DDIM  (OMICS * GENES)   // 12000
#define HDIM  64
#define ODIM  16
#define GHID  128      // gate hidden
#define CHID  8
#define NCLS  5
#define TOPK  3
#define BNEPS 1e-5f
#define NENT  (BATCH * TOPK)    // 768 expert work items
#define MAXTILE 288             // max sum of ceil(cnt_p/4)
#define NSEG  4                 // gene-split factor

// gate GEMM split-K config
#define KSPLIT 50
#define KC     80     // 50*80 = 4000
#define KB     16
#define GEMM_BLOCKS (BATCH / 64 * KSPLIT)   // 200
#define K1_BLOCKS (GEMM_BLOCKS + PATH)      // 328

// ---------------- device scratch (no allocations allowed) ----------------
__device__ float g_partial[KSPLIT * BATCH * GHID];
__device__ int   g_gene_idx[PATH * GENES];
__device__ int   g_gene_cnt[PATH];
__device__ int   g_entry[NENT];
__device__ float g_wt[NENT];
__device__ int   g_sorted[NENT];
__device__ int   g_tile_p[MAXTILE];
__device__ int   g_tile_s0[MAXTILE];
__device__ int   g_tile_n[MAXTILE];
__device__ int   g_ntiles;
__device__ float g_hpart[MAXTILE * NSEG * 4 * HDIM];   // partial h per (tile, seg, sample)
__device__ float g_contrib[NENT * ODIM];

// =============== K1: fused gene-list compaction + gate GEMM ===============
__global__ void __launch_bounds__(256)
k1_fused(const float* __restrict__ gene_mask,
         const float* __restrict__ x,
         const float* __restrict__ w) {
    __shared__ float As[KB][64];
    __shared__ float Bs[KB][GHID];
    __shared__ int sbase;
    __shared__ int wcnt[8];
    __shared__ int woff[8];

    int t = threadIdx.x;

    if (blockIdx.x < GEMM_BLOCKS) {
        int b0 = (blockIdx.x & 3) * 64;
        int k0 = (blockIdx.x >> 2) * KC;
        int rgrp = t >> 5;
        int cgrp = t & 31;

        float acc[8][4];
        #pragma unroll
        for (int i = 0; i < 8; i++)
            #pragma unroll
            for (int j = 0; j < 4; j++) acc[i][j] = 0.0f;

        for (int kb = 0; kb < KC; kb += KB) {
            int kbase = k0 + kb;
            {
                int r = t >> 2;
                int kq = (t & 3) * 4;
                float4 av = *reinterpret_cast<const float4*>(
                    x + (size_t)(b0 + r) * GENES + kbase + kq);
                As[kq + 0][r] = av.x; As[kq + 1][r] = av.y;
                As[kq + 2][r] = av.z; As[kq + 3][r] = av.w;
            }
            #pragma unroll
            for (int i = 0; i < 2; i++) {
                int f = t + i * 256;
                int kk = f >> 5;
                int c = (f & 31) * 4;
                *reinterpret_cast<float4*>(&Bs[kk][c]) =
                    *reinterpret_cast<const float4*>(w + (size_t)(kbase + kk) * GHID + c);
            }
            __syncthreads();
            #pragma unroll
            for (int kk = 0; kk < KB; kk++) {
                float4 b4 = *reinterpret_cast<const float4*>(&Bs[kk][cgrp * 4]);
                float4 a0 = *reinterpret_cast<const float4*>(&As[kk][rgrp * 8]);
                float4 a1 = *reinterpret_cast<const float4*>(&As[kk][rgrp * 8 + 4]);
                float av[8] = {a0.x, a0.y, a0.z, a0.w, a1.x, a1.y, a1.z, a1.w};
                float bv[4] = {b4.x, b4.y, b4.z, b4.w};
                #pragma unroll
                for (int i = 0; i < 8; i++)
                    #pragma unroll
                    for (int j = 0; j < 4; j++)
                        acc[i][j] = fmaf(av[i], bv[j], acc[i][j]);
            }
            __syncthreads();
        }
        float* out = g_partial + (size_t)(blockIdx.x >> 2) * (BATCH * GHID);
        #pragma unroll
        for (int i = 0; i < 8; i++) {
            *reinterpret_cast<float4*>(
                out + (size_t)(b0 + rgrp * 8 + i) * GHID + cgrp * 4) =
                make_float4(acc[i][0], acc[i][1], acc[i][2], acc[i][3]);
        }
    } else {
        int p = blockIdx.x - GEMM_BLOCKS;
        int wid = t >> 5, lane = t & 31;
        if (t == 0) sbase = 0;
        __syncthreads();
        for (int g0 = 0; g0 < GENES; g0 += 256) {
            int g = g0 + t;
            bool pred = (g < GENES) && (gene_mask[(size_t)g * PATH + p] != 0.0f);
            unsigned m = __ballot_sync(0xffffffffu, pred);
            if (lane == 0) wcnt[wid] = __popc(m);
            __syncthreads();
            if (t == 0) {
                int s = sbase;
                #pragma unroll
                for (int w8 = 0; w8 < 8; w8++) { woff[w8] = s; s += wcnt[w8]; }
                sbase = s;
            }
            __syncthreads();
            if (pred) {
                int pos = woff[wid] + __popc(m & ((1u << lane) - 1u));
                g_gene_idx[p * GENES + pos] = g;
            }
            __syncthreads();
        }
        if (t == 0) g_gene_cnt[p] = sbase;
    }
}

// =============== K2: fused gate finish (reduce + relu + layer2 + top3) ===============
__global__ void __launch_bounds__(128)
k2_gate_finish(const float* __restrict__ gb1,
               const float* __restrict__ w2,
               const float* __restrict__ b2g,
               float* __restrict__ out_gw) {
    __shared__ float hid[GHID];
    __shared__ float lg[PATH];
    __shared__ float sv[TOPK];
    __shared__ int   si[TOPK];
    int b = blockIdx.x;
    int p = threadIdx.x;

    float s = 0.0f;
    #pragma unroll
    for (int sp = 0; sp < KSPLIT; sp++)
        s += g_partial[(size_t)sp * (BATCH * GHID) + b * GHID + p];
    s += gb1[p];
    hid[p] = fmaxf(s, 0.0f);
    __syncthreads();

    float acc = b2g[p];
    #pragma unroll 8
    for (int k = 0; k < GHID; k++)
        acc = fmaf(hid[k], __ldg(w2 + (size_t)k * PATH + p), acc);
    lg[p] = acc;
    __syncthreads();

    if (p < 32) {
        float v[4];
        #pragma unroll
        for (int q = 0; q < 4; q++) v[q] = lg[p + q * 32];
        #pragma unroll
        for (int k = 0; k < TOPK; k++) {
            float bv = -1e30f; int bi = 0x7fffffff;
            #pragma unroll
            for (int q = 0; q < 4; q++) {
                int idq = p + q * 32;
                if (v[q] > bv || (v[q] == bv && idq < bi)) { bv = v[q]; bi = idq; }
            }
            #pragma unroll
            for (int off = 16; off; off >>= 1) {
                float ov = __shfl_xor_sync(0xffffffffu, bv, off);
                int oi = __shfl_xor_sync(0xffffffffu, bi, off);
                if (ov > bv || (ov == bv && oi < bi)) { bv = ov; bi = oi; }
            }
            if (p == 0) { sv[k] = bv; si[k] = bi; }
            #pragma unroll
            for (int q = 0; q < 4; q++)
                if (p + q * 32 == bi) v[q] = -1e30f;
        }
    }
    __syncthreads();

    float val = 0.0f;
    #pragma unroll
    for (int k = 0; k < TOPK; k++)
        if (si[k] == p) val = 1.0f / (1.0f + expf(-sv[k]));
    out_gw[(size_t)b * PATH + p] = val;
    if (p < TOPK) {
        g_entry[b * TOPK + p] = si[p];
        g_wt[b * TOPK + p] = 1.0f / (1.0f + expf(-sv[p]));
    }
}

// =============== K3: fast sort (1 block, 128 threads, no atomics) ===============
__global__ void __launch_bounds__(128)
k3_sort() {
    __shared__ int ent_s[NENT];
    __shared__ int wsumC[4], wsumT[4];
    int tid = threadIdx.x;

    for (int e = tid; e < NENT; e += 128) ent_s[e] = g_entry[e];
    __syncthreads();

    int p = tid;
    int cnt = 0;
    for (int e = 0; e < NENT; e++) cnt += (ent_s[e] == p);
    int nt = (cnt + 3) >> 2;

    int lane = tid & 31, wrp = tid >> 5;
    int incC = cnt, incT = nt;
    #pragma unroll
    for (int o = 1; o < 32; o <<= 1) {
        int cc = __shfl_up_sync(0xffffffffu, incC, o);
        int tt = __shfl_up_sync(0xffffffffu, incT, o);
        if (lane >= o) { incC += cc; incT += tt; }
    }
    if (lane == 31) { wsumC[wrp] = incC; wsumT[wrp] = incT; }
    __syncthreads();
    int baseC = 0, baseT = 0;
    #pragma unroll
    for (int wv = 0; wv < 4; wv++)
        if (wv < wrp) { baseC += wsumC[wv]; baseT += wsumT[wv]; }
    int offp  = baseC + incC - cnt;
    int toffp = baseT + incT - nt;

    int pos = offp;
    for (int e = 0; e < NENT; e++)
        if (ent_s[e] == p) g_sorted[pos++] = e;
    for (int tt = 0; tt < nt; tt++) {
        int idx = toffp + tt;
        g_tile_p[idx] = p;
        g_tile_s0[idx] = offp + 4 * tt;
        int rem = cnt - 4 * tt;
        g_tile_n[idx] = rem < 4 ? rem : 4;
    }
    __syncthreads();
    if (tid == 0)
        g_ntiles = wsumT[0] + wsumT[1] + wsumT[2] + wsumT[3];
}

// =============== K4: sparse experts — gene-outer depth-2 pipelined stream ===============
// block = (tile, gene-segment). 8 warps; lane owns h = 2*lane, 2*lane+1.
// Per gene: 1 glist LDG + 3 coalesced float2 W1 LDGs + 12 broadcast x LDGs + 24 FMA.
// Depth-2 gene pipeline: next gene's 15 data loads are in flight during this
// gene's FMAs (~150B/warp in flight). All pipeline branches are warp-uniform.
struct GeneData {
    float2 w[3];
    float4 xv[3];
};

__global__ void __launch_bounds__(256)
k4_expert(const float* __restrict__ x_rna,
          const float* __restrict__ x_cnv,
          const float* __restrict__ x_met,
          const float* __restrict__ W1) {
    int blk = blockIdx.x;
    int tnum = blk >> 2;
    int seg  = blk & 3;
    if (tnum >= g_ntiles) return;
    int p  = g_tile_p[tnum];
    int s0 = g_tile_s0[tnum];
    int n  = g_tile_n[tnum];
    if (n <= 0) return;
    int ng = g_gene_cnt[p];
    int qs = (ng * seg) >> 2;
    int qe = (ng * (seg + 1)) >> 2;

    int tid = threadIdx.x;
    int lane = tid & 31;   // h columns 2*lane, 2*lane+1
    int wrp = tid >> 5;    // warp owns genes i = qs+wrp, +8, ...

    __shared__ float red[8 * 4 * HDIM]; // [warp][sample][h]
    __shared__ int   bsh[4];

    if (tid < 4) {
        int sl = tid < n ? tid : n - 1;
        bsh[tid] = g_sorted[s0 + sl] / TOPK;
    }
    __syncthreads();
    const float* xr = x_rna + (size_t)bsh[0] * GENES;   // per-sample bases
    const float* xr1 = x_rna + (size_t)bsh[1] * GENES;
    const float* xr2 = x_rna + (size_t)bsh[2] * GENES;
    const float* xr3 = x_rna + (size_t)bsh[3] * GENES;
    const float* xc = x_cnv + (size_t)bsh[0] * GENES;
    const float* xc1 = x_cnv + (size_t)bsh[1] * GENES;
    const float* xc2 = x_cnv + (size_t)bsh[2] * GENES;
    const float* xc3 = x_cnv + (size_t)bsh[3] * GENES;
    const float* xm = x_met + (size_t)bsh[0] * GENES;
    const float* xm1 = x_met + (size_t)bsh[1] * GENES;
    const float* xm2 = x_met + (size_t)bsh[2] * GENES;
    const float* xm3 = x_met + (size_t)bsh[3] * GENES;

    const int* glist = g_gene_idx + p * GENES;
    const float* W1g = W1 + (size_t)p * DDIM * HDIM + 2 * lane;

    float acc[2][4];   // [h-of-pair][sample]
    #pragma unroll
    for (int i = 0; i < 2; i++)
        #pragma unroll
        for (int j = 0; j < 4; j++) acc[i][j] = 0.0f;

    // gene loader: 3 W1 float2 (coalesced) + 12 x scalars (broadcast)
    auto load_gene = [&](int g, GeneData& d) {
        d.w[0] = *reinterpret_cast<const float2*>(W1g + (size_t)g * HDIM);
        d.w[1] = *reinterpret_cast<const float2*>(W1g + (size_t)(GENES + g) * HDIM);
        d.w[2] = *reinterpret_cast<const float2*>(W1g + (size_t)(2 * GENES + g) * HDIM);
        d.xv[0] = make_float4(__ldg(xr + g), __ldg(xr1 + g), __ldg(xr2 + g), __ldg(xr3 + g));
        d.xv[1] = make_float4(__ldg(xc + g), __ldg(xc1 + g), __ldg(xc2 + g), __ldg(xc3 + g));
        d.xv[2] = make_float4(__ldg(xm + g), __ldg(xm1 + g), __ldg(xm2 + g), __ldg(xm3 + g));
    };
    auto fma_gene = [&](const GeneData& d) {
        #pragma unroll
        for (int omic = 0; omic < OMICS; omic++) {
            float4 x4 = d.xv[omic];
            float2 w2v = d.w[omic];
            acc[0][0] = fmaf(w2v.x, x4.x, acc[0][0]);
            acc[0][1] = fmaf(w2v.x, x4.y, acc[0][1]);
            acc[0][2] = fmaf(w2v.x, x4.z, acc[0][2]);
            acc[0][3] = fmaf(w2v.x, x4.w, acc[0][3]);
            acc[1][0] = fmaf(w2v.y, x4.x, acc[1][0]);
            acc[1][1] = fmaf(w2v.y, x4.y, acc[1][1]);
            acc[1][2] = fmaf(w2v.y, x4.z, acc[1][2]);
            acc[1][3] = fmaf(w2v.y, x4.w, acc[1][3]);
        }
    };

    // depth-2 gene pipeline (all control warp-uniform: i depends only on wrp)
    int i = qs + wrp;
    if (i < qe) {
        GeneData cur, nxt;
        int g0 = __ldg(glist + i);
        load_gene(g0, cur);
        int i1 = i + 8;
        while (i1 < qe) {
            int g1 = __ldg(glist + i1);
            load_gene(g1, nxt);
            fma_gene(cur);
            cur = nxt;
            i1 += 8;
        }
        fma_gene(cur);
    }

    // store per-warp partials: red[wrp][sm][h] (float2, 8B aligned)
    #pragma unroll
    for (int sm = 0; sm < 4; sm++) {
        *reinterpret_cast<float2*>(
            &red[(wrp * 4 + sm) * HDIM + 2 * lane]) =
            make_float2(acc[0][sm], acc[1][sm]);
    }
    __syncthreads();

    // reduce across 8 warps (ascending order, deterministic): thread = (sm, hh)
    {
        int sm = tid >> 6;      // 0..3
        int hh = tid & 63;
        float a = 0.0f;
        #pragma unroll
        for (int w8 = 0; w8 < 8; w8++)
            a += red[(w8 * 4 + sm) * HDIM + hh];
        float* hp = g_hpart + ((size_t)(tnum * NSEG + seg) * 4) * HDIM;
        hp[sm * HDIM + hh] = a;
    }
}

// =============== K4b: finish — reduce segments + BN + ReLU + W2 + weight ===============
__global__ void __launch_bounds__(256)
k4b_finish(const float* __restrict__ b1,
           const float* __restrict__ bn_gamma,
           const float* __restrict__ bn_beta,
           const float* __restrict__ bn_mean,
           const float* __restrict__ bn_var,
           const float* __restrict__ W2,
           const float* __restrict__ b2) {
    int tnum = blockIdx.x;
    if (tnum >= g_ntiles) return;
    int p  = g_tile_p[tnum];
    int s0 = g_tile_s0[tnum];
    int n  = g_tile_n[tnum];
    if (n <= 0) return;
    int tid = threadIdx.x;

    __shared__ float hsm[4][HDIM];
    __shared__ float w2s[HDIM * ODIM];
    __shared__ int   es[4];

    if (tid < 4) {
        int sl = tid < n ? tid : n - 1;
        es[tid] = g_sorted[s0 + sl];
    }
    const float* W2p = W2 + (size_t)p * HDIM * ODIM;
    for (int j = tid; j < HDIM * ODIM; j += 256) w2s[j] = W2p[j];

    {
        int sm = tid >> 6;       // 0..3
        int hh = tid & 63;
        const float* hp = g_hpart + (size_t)tnum * NSEG * 4 * HDIM;
        float a = 0.0f;
        #pragma unroll
        for (int q = 0; q < NSEG; q++)
            a += hp[(q * 4 + sm) * HDIM + hh];
        a += b1[p * HDIM + hh];
        float scale = bn_gamma[p * HDIM + hh] * rsqrtf(bn_var[p * HDIM + hh] + BNEPS);
        a = (a - bn_mean[p * HDIM + hh]) * scale + bn_beta[p * HDIM + hh];
        hsm[sm][hh] = fmaxf(a, 0.0f);
    }
    __syncthreads();

    if (tid < 64) {
        int sm = tid >> 4;
        int o = tid & 15;
        if (sm < n) {
            float sum = 0.0f;
            #pragma unroll 8
            for (int h2 = 0; h2 < HDIM; h2++)
                sum = fmaf(hsm[sm][h2], w2s[h2 * ODIM + o], sum);
            sum += b2[p * ODIM + o];
            int e = es[sm];
            g_contrib[(size_t)e * ODIM + o] = sum * g_wt[e];
        }
    }
}

// =============== K5: classifier ===============
__global__ void __launch_bounds__(256)
k5_classifier(const float* __restrict__ cw1,
              const float* __restrict__ cb1,
              const float* __restrict__ cw2,
              const float* __restrict__ cb2,
              float* __restrict__ out_logits) {
    int b = threadIdx.x;
    float feat[ODIM];
    #pragma unroll
    for (int o = 0; o < ODIM; o++)
        feat[o] = g_contrib[((size_t)b * TOPK + 0) * ODIM + o]
                + g_contrib[((size_t)b * TOPK + 1) * ODIM + o]
                + g_contrib[((size_t)b * TOPK + 2) * ODIM + o];
    float h8[CHID];
    #pragma unroll
    for (int c = 0; c < CHID; c++) {
        float s = cb1[c];
        #pragma unroll
        for (int o = 0; o < ODIM; o++)
            s = fmaf(feat[o], __ldg(cw1 + o * CHID + c), s);
        h8[c] = fmaxf(s, 0.0f);
    }
    #pragma unroll
    for (int c5 = 0; c5 < NCLS; c5++) {
        float s = cb2[c5];
        #pragma unroll
        for (int c = 0; c < CHID; c++)
            s = fmaf(h8[c], __ldg(cw2 + c * NCLS + c5), s);
        out_logits[(size_t)b * NCLS + c5] = s;
    }
}

// ---------------- launch ----------------
extern "C" void kernel_launch(void* const* d_in, const int* in_sizes, int n_in,
                              void* d_out, int out_size) {
    const float* x_rna    = (const float*)d_in[0];
    const float* x_cnv    = (const float*)d_in[1];
    const float* x_met    = (const float*)d_in[2];
    const float* gene_mask= (const float*)d_in[3];
    const float* gate_w1  = (const float*)d_in[4];
    const float* gate_b1  = (const float*)d_in[5];
    const float* gate_w2  = (const float*)d_in[6];
    const float* gate_b2  = (const float*)d_in[7];
    const float* W1       = (const float*)d_in[8];
    const float* b1       = (const float*)d_in[9];
    const float* bn_gamma = (const float*)d_in[10];
    const float* bn_beta  = (const float*)d_in[11];
    const float* bn_mean  = (const float*)d_in[12];
    const float* bn_var   = (const float*)d_in[13];
    const float* W2       = (const float*)d_in[14];
    const float* b2       = (const float*)d_in[15];
    const float* cls_w1   = (const float*)d_in[16];
    const float* cls_b1   = (const float*)d_in[17];
    const float* cls_w2   = (const float*)d_in[18];
    const float* cls_b2   = (const float*)d_in[19];
    float* out = (float*)d_out;
    float* out_logits = out;
    float* out_gw = out + BATCH * NCLS;

    k1_fused<<<K1_BLOCKS, 256>>>(gene_mask, x_rna, gate_w1);
    k2_gate_finish<<<BATCH, GHID>>>(gate_b1, gate_w2, gate_b2, out_gw);
    k3_sort<<<1, 128>>>();
    k4_expert<<<MAXTILE * NSEG, 256>>>(x_rna, x_cnv, x_met, W1);
    k4b_finish<<<MAXTILE, 256>>>(b1, bn_gamma, bn_beta, bn_mean, bn_var, W2, b2);
    k5_classifier<<<1, BATCH>>>(cls_w1, cls_b1, cls_w2, cls_b2, out_logits);
}